// round 9
// baseline (speedup 1.0000x reference)
#include <cuda_runtime.h>
#include <math.h>
#include <stdint.h>

#define BATCH 8
#define HEADS 8
#define SEQ   1024
#define DIM   512
#define DH    64
#define INNER 512
#define BH    (BATCH*HEADS)   // 64

// ---------------- scratch (no allocations allowed) ----------------
__device__ float g_xn[(size_t)BATCH*SEQ*DIM];      // 16 MB
__device__ float g_q [(size_t)BH*SEQ*DH];          // 16 MB
__device__ float g_kt[(size_t)BH*DH*SEQ];          // 16 MB (K pre-transposed)
__device__ float g_v [(size_t)BH*SEQ*DH];          // 16 MB
__device__ float g_o [(size_t)BATCH*SEQ*INNER];    // 16 MB

// ---------------- helpers ----------------
__device__ __forceinline__ uint32_t f2tf32(float f) {
    uint32_t u;
    asm("cvt.rna.tf32.f32 %0, %1;" : "=r"(u) : "f"(f));
    return u;
}

__device__ __forceinline__ void mma_tf32(float c[4],
                                         const uint32_t a[4],
                                         const uint32_t b[2]) {
    asm volatile(
        "mma.sync.aligned.m16n8k8.row.col.f32.tf32.tf32.f32 "
        "{%0,%1,%2,%3}, {%4,%5,%6,%7}, {%8,%9}, {%0,%1,%2,%3};"
        : "+f"(c[0]), "+f"(c[1]), "+f"(c[2]), "+f"(c[3])
        : "r"(a[0]), "r"(a[1]), "r"(a[2]), "r"(a[3]),
          "r"(b[0]), "r"(b[1]));
}

// ---------------- LayerNorm ----------------
__global__ void ln_kernel(const float* __restrict__ x,
                          const float* __restrict__ gam,
                          const float* __restrict__ bet) {
    int row = blockIdx.x;
    const float* xr = x + (size_t)row * DIM;
    float* outp = g_xn + (size_t)row * DIM;
    int t = threadIdx.x;                      // 128 threads
    float v[4];
    float s = 0.f, ss = 0.f;
#pragma unroll
    for (int i = 0; i < 4; i++) {
        v[i] = xr[t + i*128];
        s  += v[i];
        ss += v[i]*v[i];
    }
#pragma unroll
    for (int o = 16; o; o >>= 1) {
        s  += __shfl_xor_sync(0xffffffffu, s, o);
        ss += __shfl_xor_sync(0xffffffffu, ss, o);
    }
    __shared__ float sb[2][4];
    int warp = t >> 5, lane = t & 31;
    if (lane == 0) { sb[0][warp] = s; sb[1][warp] = ss; }
    __syncthreads();
    s  = sb[0][0]+sb[0][1]+sb[0][2]+sb[0][3];
    ss = sb[1][0]+sb[1][1]+sb[1][2]+sb[1][3];
    float mean = s * (1.0f/DIM);
    float var  = ss * (1.0f/DIM) - mean*mean;
    float inv  = rsqrtf(var + 1e-5f);
#pragma unroll
    for (int i = 0; i < 4; i++) {
        int c = t + i*128;
        outp[c] = (v[i]-mean)*inv*gam[c] + bet[c];
    }
}

// ---------------- TF32 tensor-core GEMM core (for QKV / out) ----------------
template<int BM,int BN,int BK,int WM,int WN>
__device__ __forceinline__ void mma_gemm_core(
    const float* __restrict__ A, const float* __restrict__ B,
    int K, int lda, int ldb, int row0, int col0,
    float acc[WM/16][WN/8][4])
{
    constexpr int MI = WM/16, NI = WN/8;
    constexpr int WCOLS = BN/WN;
    __shared__ uint32_t As[BM][BK+4];
    __shared__ uint32_t Bs[BK][BN+8];
    const int tid  = threadIdx.x;
    const int lane = tid & 31, wid = tid >> 5;
    const int g = lane >> 2, tg = lane & 3;
    const int wr = wid / WCOLS, wc = wid % WCOLS;

#pragma unroll
    for (int mi = 0; mi < MI; mi++)
#pragma unroll
        for (int ni = 0; ni < NI; ni++)
#pragma unroll
            for (int rr = 0; rr < 4; rr++) acc[mi][ni][rr] = 0.f;

    for (int k0 = 0; k0 < K; k0 += BK) {
#pragma unroll
        for (int s = 0; s < BM*BK/4; s += 256) {
            int slot = s + tid;
            int r  = slot / (BK/4);
            int kq = slot % (BK/4);
            float4 v = *(const float4*)(A + (size_t)(row0+r)*lda + k0 + kq*4);
            As[r][kq*4+0] = f2tf32(v.x);
            As[r][kq*4+1] = f2tf32(v.y);
            As[r][kq*4+2] = f2tf32(v.z);
            As[r][kq*4+3] = f2tf32(v.w);
        }
#pragma unroll
        for (int s = 0; s < BK*BN/4; s += 256) {
            int slot = s + tid;
            int kr = slot / (BN/4);
            int nc = slot % (BN/4);
            float4 v = *(const float4*)(B + (size_t)(k0+kr)*ldb + col0 + nc*4);
            uint4 u;
            u.x = f2tf32(v.x); u.y = f2tf32(v.y);
            u.z = f2tf32(v.z); u.w = f2tf32(v.w);
            *(uint4*)&Bs[kr][nc*4] = u;
        }
        __syncthreads();
#pragma unroll
        for (int ks = 0; ks < BK/8; ks++) {
            uint32_t af[MI][4], bf[NI][2];
#pragma unroll
            for (int mi = 0; mi < MI; mi++) {
                int m0 = wr*WM + mi*16;
                af[mi][0] = As[m0+g  ][ks*8+tg  ];
                af[mi][1] = As[m0+g+8][ks*8+tg  ];
                af[mi][2] = As[m0+g  ][ks*8+tg+4];
                af[mi][3] = As[m0+g+8][ks*8+tg+4];
            }
#pragma unroll
            for (int ni = 0; ni < NI; ni++) {
                int n0 = wc*WN + ni*8;
                bf[ni][0] = Bs[ks*8+tg  ][n0+g];
                bf[ni][1] = Bs[ks*8+tg+4][n0+g];
            }
#pragma unroll
            for (int mi = 0; mi < MI; mi++)
#pragma unroll
                for (int ni = 0; ni < NI; ni++)
                    mma_tf32(acc[mi][ni], af[mi], bf[ni]);
        }
        __syncthreads();
    }
}

// ---------------- QKV projection + scatter epilogue ----------------
__global__ __launch_bounds__(256) void qkv_gemm(const float* __restrict__ w,
                                                const float* __restrict__ bias) {
    constexpr int WM = 64, WN = 32, MI = WM/16, NI = WN/8;
    float acc[MI][NI][4];
    int row0 = blockIdx.y*128, col0 = blockIdx.x*128;
    mma_gemm_core<128,128,16,WM,WN>(g_xn, w, DIM, DIM, 3*INNER, row0, col0, acc);

    const int lane = threadIdx.x & 31, wid = threadIdx.x >> 5;
    const int g = lane >> 2, tg = lane & 3;
    const int wr = wid / 4, wc = wid % 4;
#pragma unroll
    for (int mi = 0; mi < MI; mi++)
#pragma unroll
        for (int ni = 0; ni < NI; ni++)
#pragma unroll
            for (int rr = 0; rr < 4; rr++) {
                int r = row0 + wr*WM + mi*16 + g + (rr>>1)*8;
                int c = col0 + wc*WN + ni*8 + tg*2 + (rr&1);
                float val = acc[mi][ni][rr] + bias[c];
                int bb = r >> 10, nn = r & 1023;
                int sec = c >> 9, rem = c & 511;
                int h = rem >> 6, d = rem & 63;
                int bh = bb*HEADS + h;
                if (sec == 0)
                    g_q[((size_t)bh*SEQ + nn)*DH + d] = val;
                else if (sec == 1)
                    g_kt[((size_t)bh*DH + d)*SEQ + nn] = val;   // transposed
                else
                    g_v[((size_t)bh*SEQ + nn)*DH + d] = val;
            }
}

// =====================================================================
// Fused attention v2: S tile lives in SHARED MEMORY (32 x 1024 fp32).
// Grid (32, 64): CTA = one image row of queries (32) x all 1024 keys,
// 512 threads / 16 warps.
//   Phase 1: scores mma  -> S (all warps, 64 keys each)
//   Phase 2: 4-region softmax on S rows (R5-proven math), writes tf32 bits
//   Phase 3: AV mma, warp = one m16n8 output tile over full K, V chunked
// =====================================================================
#define S_LD   1036     // fp32 words per S row (pad: 12g+tg banks distinct)
#define KT_LD  1032     // pad: 8tg+g distinct
#define V_LD   68       // pad: 4tg+g distinct
#define Q_LD   68

#define SM_S_OFF  0
#define SM_Q_OFF  (32*S_LD*4)                    // 132608
#define SM_KV_OFF (SM_Q_OFF + 32*Q_LD*4)         // 141312
#define SMEM2_TOTAL (SM_KV_OFF + 16*KT_LD*4)     // 207360 (V chunk 34816 fits)

__global__ __launch_bounds__(512, 1) void attn_fused2() {
    extern __shared__ char smem[];
    uint32_t (*S)  [S_LD]  = (uint32_t(*)[S_LD]) (smem + SM_S_OFF);
    uint32_t (*Qs) [Q_LD]  = (uint32_t(*)[Q_LD]) (smem + SM_Q_OFF);
    uint32_t (*KTs)[KT_LD] = (uint32_t(*)[KT_LD])(smem + SM_KV_OFF);
    uint32_t (*Vs) [V_LD]  = (uint32_t(*)[V_LD]) (smem + SM_KV_OFF);

    const int qb = blockIdx.x;            // query image-row r (0..31)
    const int z  = blockIdx.y;            // bh
    const int tid = threadIdx.x, lane = tid & 31, wid = tid >> 5;
    const int g = lane >> 2, tg = lane & 3;

    const float* Qg  = g_q  + (size_t)z*SEQ*DH + (size_t)qb*32*DH;
    const float* KTg = g_kt + (size_t)z*DH*SEQ;
    const float* Vg  = g_v  + (size_t)z*SEQ*DH;

    // ---- load Q tile 32x64 tf32 (512 float4 / 512 threads) ----
    {
        int m = tid >> 4, k4 = tid & 15;
        float4 v = *(const float4*)(Qg + m*DH + k4*4);
        Qs[m][k4*4+0] = f2tf32(v.x);
        Qs[m][k4*4+1] = f2tf32(v.y);
        Qs[m][k4*4+2] = f2tf32(v.z);
        Qs[m][k4*4+3] = f2tf32(v.w);
    }

    // ---- Phase 1: S = Q @ K^T ; warp owns 64 keys ----
    float acc[2][8][4];
#pragma unroll
    for (int mi = 0; mi < 2; mi++)
#pragma unroll
        for (int ni = 0; ni < 8; ni++)
#pragma unroll
            for (int rr = 0; rr < 4; rr++) acc[mi][ni][rr] = 0.f;

    const int n0w = wid << 6;             // warp's first key
    for (int kc = 0; kc < 4; kc++) {
        // load KT rows [kc*16, +16) x 1024 keys (4096 float4 / 512 thr = 8)
#pragma unroll
        for (int i = 0; i < 8; i++) {
            int idx = tid + i*512;
            int r = idx >> 8, c4 = idx & 255;
            float4 v = *(const float4*)(KTg + (size_t)(kc*16 + r)*SEQ + c4*4);
            uint4 u;
            u.x = f2tf32(v.x); u.y = f2tf32(v.y);
            u.z = f2tf32(v.z); u.w = f2tf32(v.w);
            *(uint4*)&KTs[r][c4*4] = u;
        }
        __syncthreads();
#pragma unroll
        for (int ks = 0; ks < 2; ks++) {
            int kq = kc*16 + ks*8;        // col into Qs
            uint32_t af[2][4];
#pragma unroll
            for (int mi = 0; mi < 2; mi++) {
                af[mi][0] = Qs[mi*16+g  ][kq+tg  ];
                af[mi][1] = Qs[mi*16+g+8][kq+tg  ];
                af[mi][2] = Qs[mi*16+g  ][kq+tg+4];
                af[mi][3] = Qs[mi*16+g+8][kq+tg+4];
            }
#pragma unroll
            for (int ni = 0; ni < 8; ni++) {
                uint32_t bf[2];
                int n0 = n0w + ni*8;
                bf[0] = KTs[ks*8+tg  ][n0+g];
                bf[1] = KTs[ks*8+tg+4][n0+g];
                mma_tf32(acc[0][ni], af[0], bf);
                mma_tf32(acc[1][ni], af[1], bf);
            }
        }
        __syncthreads();
    }
    // scale + write scores to S (fp32 bits)
#pragma unroll
    for (int mi = 0; mi < 2; mi++)
#pragma unroll
        for (int ni = 0; ni < 8; ni++)
#pragma unroll
            for (int rr = 0; rr < 4; rr++) {
                int row = mi*16 + g + (rr>>1)*8;
                int col = n0w + ni*8 + tg*2 + (rr&1);
                S[row][col] = __float_as_uint(acc[mi][ni][rr] * 0.125f);
            }
    __syncthreads();

    // ---- Phase 2: 4-region softmax, warp per 2 rows (R5 math) ----
#pragma unroll
    for (int rw = 0; rw < 2; rw++) {
        int m = wid*2 + rw;               // local row == query col index c
        int kj = lane;
        float e[32];
        float M = -1e30f;
#pragma unroll
        for (int ki = 0; ki < 32; ki++) {
            e[ki] = __uint_as_float(S[m][ki*32 + kj]);
            M = fmaxf(M, e[ki]);
        }
#pragma unroll
        for (int o = 16; o; o >>= 1)
            M = fmaxf(M, __shfl_xor_sync(0xffffffffu, M, o));
        float cle = 0.f, cge = 0.f;
#pragma unroll
        for (int ki = 0; ki < 32; ki++) {
            e[ki] = __expf(e[ki] - M);
            if (ki <= qb) cle += e[ki];
            if (ki >= qb) cge += e[ki];
        }
        bool jle = (kj <= m), jge = (kj >= m);
        float z00 = jle ? cle : 0.f;
        float z01 = jge ? cle : 0.f;
        float z10 = jle ? cge : 0.f;
        float z11 = jge ? cge : 0.f;
#pragma unroll
        for (int o = 16; o; o >>= 1) {
            z00 += __shfl_xor_sync(0xffffffffu, z00, o);
            z01 += __shfl_xor_sync(0xffffffffu, z01, o);
            z10 += __shfl_xor_sync(0xffffffffu, z10, o);
            z11 += __shfl_xor_sync(0xffffffffu, z11, o);
        }
        float ct = (jle ? 0.25f/z00 : 0.f) + (jge ? 0.25f/z01 : 0.f);
        float cb = (jle ? 0.25f/z10 : 0.f) + (jge ? 0.25f/z11 : 0.f);
#pragma unroll
        for (int ki = 0; ki < 32; ki++) {
            float wv = e[ki] * ((ki <= qb ? ct : 0.f) + (ki >= qb ? cb : 0.f));
            S[m][ki*32 + kj] = f2tf32(wv);   // tf32 bits, ready as A operand
        }
    }
    __syncthreads();

    // ---- Phase 3: O = W @ V ; warp owns one m16n8 tile over full K ----
    float acc2[4] = {0.f, 0.f, 0.f, 0.f};
    const int m0 = (wid >> 3) * 16;       // 0 or 16
    const int n0 = (wid & 7) * 8;         // d-tile
    for (int kc = 0; kc < 8; kc++) {
        // load V chunk [128][64] (2048 float4 / 512 thr = 4)
#pragma unroll
        for (int i = 0; i < 4; i++) {
            int idx = tid + i*512;
            int k = idx >> 4, d4 = idx & 15;
            float4 v = *(const float4*)(Vg + (size_t)(kc*128 + k)*DH + d4*4);
            uint4 u;
            u.x = f2tf32(v.x); u.y = f2tf32(v.y);
            u.z = f2tf32(v.z); u.w = f2tf32(v.w);
            *(uint4*)&Vs[k][d4*4] = u;
        }
        __syncthreads();
#pragma unroll
        for (int kt = 0; kt < 16; kt++) {
            int kb = kc*128 + kt*8;
            uint32_t af[4], bf[2];
            af[0] = S[m0+g  ][kb+tg  ];
            af[1] = S[m0+g+8][kb+tg  ];
            af[2] = S[m0+g  ][kb+tg+4];
            af[3] = S[m0+g+8][kb+tg+4];
            bf[0] = Vs[kt*8+tg  ][n0+g];
            bf[1] = Vs[kt*8+tg+4][n0+g];
            mma_tf32(acc2, af, bf);
        }
        __syncthreads();
    }

    // epilogue: O -> g_o[b][q][h*64+d]
    {
        int bb = z >> 3, h = z & 7;
#pragma unroll
        for (int rr = 0; rr < 4; rr++) {
            int m = m0 + g + (rr>>1)*8;
            int d = n0 + tg*2 + (rr&1);
            g_o[((size_t)bb*SEQ + qb*32 + m)*INNER + h*DH + d] = acc2[rr];
        }
    }
}

// ---------------- output projection ----------------
__global__ __launch_bounds__(256) void out_gemm(const float* __restrict__ w,
                                                const float* __restrict__ bias,
                                                float* __restrict__ outp) {
    constexpr int WM = 64, WN = 32, MI = WM/16, NI = WN/8;
    float acc[MI][NI][4];
    int row0 = blockIdx.y*128, col0 = blockIdx.x*128;
    mma_gemm_core<128,128,16,WM,WN>(g_o, w, INNER, INNER, DIM, row0, col0, acc);
    const int lane = threadIdx.x & 31, wid = threadIdx.x >> 5;
    const int g = lane >> 2, tg = lane & 3;
    const int wr = wid / 4, wc = wid % 4;
#pragma unroll
    for (int mi = 0; mi < MI; mi++)
#pragma unroll
        for (int ni = 0; ni < NI; ni++)
#pragma unroll
            for (int rr = 0; rr < 4; rr++) {
                int r = row0 + wr*WM + mi*16 + g + (rr>>1)*8;
                int c = col0 + wc*WN + ni*8 + tg*2 + (rr&1);
                outp[(size_t)r*DIM + c] = acc[mi][ni][rr] + bias[c];
            }
}

// ---------------- launch ----------------
extern "C" void kernel_launch(void* const* d_in, const int* in_sizes, int n_in,
                              void* d_out, int out_size) {
    const float* x     = (const float*)d_in[0];
    const float* ln_g  = (const float*)d_in[1];
    const float* ln_b  = (const float*)d_in[2];
    const float* w_qkv = (const float*)d_in[3];
    const float* b_qkv = (const float*)d_in[4];
    const float* w_out = (const float*)d_in[5];
    const float* b_out = (const float*)d_in[6];
    float* outp = (float*)d_out;

    static bool attr_set = false;
    if (!attr_set) {
        cudaFuncSetAttribute(attn_fused2,
                             cudaFuncAttributeMaxDynamicSharedMemorySize,
                             SMEM2_TOTAL);
        attr_set = true;
    }

    ln_kernel<<<BATCH*SEQ, 128>>>(x, ln_g, ln_b);
    qkv_gemm<<<dim3((3*INNER)/128, (BATCH*SEQ)/128), 256>>>(w_qkv, b_qkv);
    attn_fused2<<<dim3(32, BH), 512, SMEM2_TOTAL>>>();
    out_gemm<<<dim3(DIM/128, (BATCH*SEQ)/128), 256>>>(w_out, b_out, outp);
}

// round 10
// speedup vs baseline: 1.1703x; 1.1703x over previous
#include <cuda_runtime.h>
#include <math.h>
#include <stdint.h>

#define BATCH 8
#define HEADS 8
#define SEQ   1024
#define DIM   512
#define DH    64
#define INNER 512
#define BH    (BATCH*HEADS)   // 64

// ---------------- scratch (no allocations allowed) ----------------
__device__ float g_xn[(size_t)BATCH*SEQ*DIM];      // 16 MB
__device__ float g_q [(size_t)BH*SEQ*DH];          // 16 MB
__device__ float g_kt[(size_t)BH*DH*SEQ];          // 16 MB (K pre-transposed)
__device__ float g_v [(size_t)BH*SEQ*DH];          // 16 MB
__device__ float g_s [(size_t)BH*SEQ*SEQ];         // 256 MB (scores)
__device__ float g_stats[(size_t)BH*SEQ*8];        // 2 MB  (M, 0.25/Z x4)
__device__ float g_o [(size_t)BATCH*SEQ*INNER];    // 16 MB

// ---------------- helpers ----------------
__device__ __forceinline__ uint32_t f2tf32(float f) {
    uint32_t u;
    asm("cvt.rna.tf32.f32 %0, %1;" : "=r"(u) : "f"(f));
    return u;
}

__device__ __forceinline__ void mma_tf32(float c[4],
                                         const uint32_t a[4],
                                         const uint32_t b[2]) {
    asm volatile(
        "mma.sync.aligned.m16n8k8.row.col.f32.tf32.tf32.f32 "
        "{%0,%1,%2,%3}, {%4,%5,%6,%7}, {%8,%9}, {%0,%1,%2,%3};"
        : "+f"(c[0]), "+f"(c[1]), "+f"(c[2]), "+f"(c[3])
        : "r"(a[0]), "r"(a[1]), "r"(a[2]), "r"(a[3]),
          "r"(b[0]), "r"(b[1]));
}

// ---------------- LayerNorm ----------------
__global__ void ln_kernel(const float* __restrict__ x,
                          const float* __restrict__ gam,
                          const float* __restrict__ bet) {
    int row = blockIdx.x;
    const float* xr = x + (size_t)row * DIM;
    float* outp = g_xn + (size_t)row * DIM;
    int t = threadIdx.x;                      // 128 threads
    float v[4];
    float s = 0.f, ss = 0.f;
#pragma unroll
    for (int i = 0; i < 4; i++) {
        v[i] = xr[t + i*128];
        s  += v[i];
        ss += v[i]*v[i];
    }
#pragma unroll
    for (int o = 16; o; o >>= 1) {
        s  += __shfl_xor_sync(0xffffffffu, s, o);
        ss += __shfl_xor_sync(0xffffffffu, ss, o);
    }
    __shared__ float sb[2][4];
    int warp = t >> 5, lane = t & 31;
    if (lane == 0) { sb[0][warp] = s; sb[1][warp] = ss; }
    __syncthreads();
    s  = sb[0][0]+sb[0][1]+sb[0][2]+sb[0][3];
    ss = sb[1][0]+sb[1][1]+sb[1][2]+sb[1][3];
    float mean = s * (1.0f/DIM);
    float var  = ss * (1.0f/DIM) - mean*mean;
    float inv  = rsqrtf(var + 1e-5f);
#pragma unroll
    for (int i = 0; i < 4; i++) {
        int c = t + i*128;
        outp[c] = (v[i]-mean)*inv*gam[c] + bet[c];
    }
}

// ============ double-buffered TF32 GEMM core (qkv / out) ============
// 256 threads, one __syncthreads per k-iter, LDG prefetch 1 tile ahead.
template<int BM,int BN,int BK,int WM,int WN>
__device__ __forceinline__ void gemm_db(
    const float* __restrict__ A, const float* __restrict__ B,
    int K, int lda, int ldb, int row0, int col0,
    float acc[WM/16][WN/8][4])
{
    constexpr int MI = WM/16, NI = WN/8;
    constexpr int WCOLS = BN/WN;
    constexpr int AL = BM*BK/(4*256);
    constexpr int BL = BK*BN/(4*256);
    __shared__ uint32_t As[2][BM][BK+4];
    __shared__ uint32_t Bs[2][BK][BN+8];
    const int tid = threadIdx.x, lane = tid & 31, wid = tid >> 5;
    const int g = lane >> 2, tg = lane & 3;
    const int wr = wid / WCOLS, wc = wid % WCOLS;

#pragma unroll
    for (int mi = 0; mi < MI; mi++)
#pragma unroll
        for (int ni = 0; ni < NI; ni++)
#pragma unroll
            for (int rr = 0; rr < 4; rr++) acc[mi][ni][rr] = 0.f;

    // preload tile 0
#pragma unroll
    for (int i = 0; i < AL; i++) {
        int idx = tid + i*256;
        int r = idx / (BK/4), kq = idx % (BK/4);
        float4 v = *(const float4*)(A + (size_t)(row0+r)*lda + kq*4);
        As[0][r][kq*4+0] = f2tf32(v.x);
        As[0][r][kq*4+1] = f2tf32(v.y);
        As[0][r][kq*4+2] = f2tf32(v.z);
        As[0][r][kq*4+3] = f2tf32(v.w);
    }
#pragma unroll
    for (int i = 0; i < BL; i++) {
        int idx = tid + i*256;
        int kr = idx / (BN/4), nc = idx % (BN/4);
        float4 v = *(const float4*)(B + (size_t)kr*ldb + col0 + nc*4);
        Bs[0][kr][nc*4+0] = f2tf32(v.x);
        Bs[0][kr][nc*4+1] = f2tf32(v.y);
        Bs[0][kr][nc*4+2] = f2tf32(v.z);
        Bs[0][kr][nc*4+3] = f2tf32(v.w);
    }
    __syncthreads();

    const int nt = K / BK;
    float4 ar[AL], br[BL];
    for (int kt = 0; kt < nt; kt++) {
        const int buf = kt & 1;
        if (kt + 1 < nt) {                 // prefetch next tile to regs
#pragma unroll
            for (int i = 0; i < AL; i++) {
                int idx = tid + i*256;
                int r = idx / (BK/4), kq = idx % (BK/4);
                ar[i] = *(const float4*)(A + (size_t)(row0+r)*lda + (kt+1)*BK + kq*4);
            }
#pragma unroll
            for (int i = 0; i < BL; i++) {
                int idx = tid + i*256;
                int kr = idx / (BN/4), nc = idx % (BN/4);
                br[i] = *(const float4*)(B + (size_t)((kt+1)*BK+kr)*ldb + col0 + nc*4);
            }
        }
#pragma unroll
        for (int ks = 0; ks < BK/8; ks++) {
            uint32_t af[MI][4], bf[NI][2];
#pragma unroll
            for (int mi = 0; mi < MI; mi++) {
                int m0 = wr*WM + mi*16;
                af[mi][0] = As[buf][m0+g  ][ks*8+tg  ];
                af[mi][1] = As[buf][m0+g+8][ks*8+tg  ];
                af[mi][2] = As[buf][m0+g  ][ks*8+tg+4];
                af[mi][3] = As[buf][m0+g+8][ks*8+tg+4];
            }
#pragma unroll
            for (int ni = 0; ni < NI; ni++) {
                int n0 = wc*WN + ni*8;
                bf[ni][0] = Bs[buf][ks*8+tg  ][n0+g];
                bf[ni][1] = Bs[buf][ks*8+tg+4][n0+g];
            }
#pragma unroll
            for (int mi = 0; mi < MI; mi++)
#pragma unroll
                for (int ni = 0; ni < NI; ni++)
                    mma_tf32(acc[mi][ni], af[mi], bf[ni]);
        }
        if (kt + 1 < nt) {                 // stage into other buffer
#pragma unroll
            for (int i = 0; i < AL; i++) {
                int idx = tid + i*256;
                int r = idx / (BK/4), kq = idx % (BK/4);
                As[buf^1][r][kq*4+0] = f2tf32(ar[i].x);
                As[buf^1][r][kq*4+1] = f2tf32(ar[i].y);
                As[buf^1][r][kq*4+2] = f2tf32(ar[i].z);
                As[buf^1][r][kq*4+3] = f2tf32(ar[i].w);
            }
#pragma unroll
            for (int i = 0; i < BL; i++) {
                int idx = tid + i*256;
                int kr = idx / (BN/4), nc = idx % (BN/4);
                Bs[buf^1][kr][nc*4+0] = f2tf32(br[i].x);
                Bs[buf^1][kr][nc*4+1] = f2tf32(br[i].y);
                Bs[buf^1][kr][nc*4+2] = f2tf32(br[i].z);
                Bs[buf^1][kr][nc*4+3] = f2tf32(br[i].w);
            }
        }
        __syncthreads();
    }
}

// ---------------- QKV projection + scatter epilogue ----------------
__global__ __launch_bounds__(256) void qkv_gemm(const float* __restrict__ w,
                                                const float* __restrict__ bias) {
    constexpr int WM = 64, WN = 32, MI = WM/16, NI = WN/8;
    float acc[MI][NI][4];
    int row0 = blockIdx.y*128, col0 = blockIdx.x*128;
    gemm_db<128,128,16,WM,WN>(g_xn, w, DIM, DIM, 3*INNER, row0, col0, acc);

    const int lane = threadIdx.x & 31, wid = threadIdx.x >> 5;
    const int g = lane >> 2, tg = lane & 3;
    const int wr = wid / 4, wc = wid % 4;
#pragma unroll
    for (int mi = 0; mi < MI; mi++)
#pragma unroll
        for (int ni = 0; ni < NI; ni++)
#pragma unroll
            for (int rr = 0; rr < 4; rr++) {
                int r = row0 + wr*WM + mi*16 + g + (rr>>1)*8;
                int c = col0 + wc*WN + ni*8 + tg*2 + (rr&1);
                float val = acc[mi][ni][rr] + bias[c];
                int bb = r >> 10, nn = r & 1023;
                int sec = c >> 9, rem = c & 511;
                int h = rem >> 6, d = rem & 63;
                int bh = bb*HEADS + h;
                if (sec == 0)
                    g_q[((size_t)bh*SEQ + nn)*DH + d] = val;
                else if (sec == 1)
                    g_kt[((size_t)bh*DH + d)*SEQ + nn] = val;   // transposed
                else
                    g_v[((size_t)bh*SEQ + nn)*DH + d] = val;
            }
}

// ---------------- scores: single-shot K=64 (per b,h) ----------------
#define SC_ALD 68
#define SC_BLD 136
#define SC_SMEM ((128*SC_ALD + 64*SC_BLD)*4)   // 69632

__global__ __launch_bounds__(256) void scores_gemm() {
    extern __shared__ uint32_t sm[];
    uint32_t (*As)[SC_ALD] = (uint32_t(*)[SC_ALD])sm;
    uint32_t (*Bs)[SC_BLD] = (uint32_t(*)[SC_BLD])(sm + 128*SC_ALD);
    const int z = blockIdx.z;
    const int row0 = blockIdx.y*128, col0 = blockIdx.x*128;
    const int tid = threadIdx.x, lane = tid & 31, wid = tid >> 5;
    const int g = lane >> 2, tg = lane & 3;
    const int wr = wid / 4, wc = wid % 4;      // WM=64, WN=32

    const float* Ag = g_q  + (size_t)z*SEQ*DH;
    const float* Bg = g_kt + (size_t)z*DH*SEQ;

    // load Q tile [128][64] : 2048 float4
#pragma unroll
    for (int i = 0; i < 8; i++) {
        int idx = tid + i*256;
        int r = idx >> 4, kq = idx & 15;
        float4 v = *(const float4*)(Ag + (size_t)(row0+r)*DH + kq*4);
        As[r][kq*4+0] = f2tf32(v.x);
        As[r][kq*4+1] = f2tf32(v.y);
        As[r][kq*4+2] = f2tf32(v.z);
        As[r][kq*4+3] = f2tf32(v.w);
    }
    // load KT tile [64][128] : 2048 float4
#pragma unroll
    for (int i = 0; i < 8; i++) {
        int idx = tid + i*256;
        int d = idx >> 5, nc = idx & 31;
        float4 v = *(const float4*)(Bg + (size_t)d*SEQ + col0 + nc*4);
        Bs[d][nc*4+0] = f2tf32(v.x);
        Bs[d][nc*4+1] = f2tf32(v.y);
        Bs[d][nc*4+2] = f2tf32(v.z);
        Bs[d][nc*4+3] = f2tf32(v.w);
    }
    __syncthreads();

    float acc[4][4][4];
#pragma unroll
    for (int mi = 0; mi < 4; mi++)
#pragma unroll
        for (int ni = 0; ni < 4; ni++)
#pragma unroll
            for (int rr = 0; rr < 4; rr++) acc[mi][ni][rr] = 0.f;

#pragma unroll
    for (int ks = 0; ks < 8; ks++) {
        uint32_t af[4][4], bf[4][2];
#pragma unroll
        for (int mi = 0; mi < 4; mi++) {
            int m0 = wr*64 + mi*16;
            af[mi][0] = As[m0+g  ][ks*8+tg  ];
            af[mi][1] = As[m0+g+8][ks*8+tg  ];
            af[mi][2] = As[m0+g  ][ks*8+tg+4];
            af[mi][3] = As[m0+g+8][ks*8+tg+4];
        }
#pragma unroll
        for (int ni = 0; ni < 4; ni++) {
            int n0 = wc*32 + ni*8;
            bf[ni][0] = Bs[ks*8+tg  ][n0+g];
            bf[ni][1] = Bs[ks*8+tg+4][n0+g];
        }
#pragma unroll
        for (int mi = 0; mi < 4; mi++)
#pragma unroll
            for (int ni = 0; ni < 4; ni++)
                mma_tf32(acc[mi][ni], af[mi], bf[ni]);
    }

    float* S = g_s + (size_t)z*SEQ*SEQ;
#pragma unroll
    for (int mi = 0; mi < 4; mi++)
#pragma unroll
        for (int ni = 0; ni < 4; ni++)
#pragma unroll
            for (int rr = 0; rr < 4; rr++) {
                int r = row0 + wr*64 + mi*16 + g + (rr>>1)*8;
                int c = col0 + wc*32 + ni*8 + tg*2 + (rr&1);
                S[(size_t)r*SEQ + c] = acc[mi][ni][rr] * 0.125f;
            }
}

// ---------------- stats: per-row M and 0.25/Z for the 4 regions --------
__global__ __launch_bounds__(256) void stats_kernel() {
    int wid = threadIdx.x >> 5, lane = threadIdx.x & 31;
    int q = blockIdx.x * 8 + wid;
    int z = blockIdx.y;
    const float* srow = g_s + ((size_t)z*SEQ + q)*SEQ;
    int r = q >> 5, c = q & 31;
    int kj = lane;

    float sv[32];
    float M = -1e30f;
#pragma unroll
    for (int ki = 0; ki < 32; ki++) {
        sv[ki] = srow[ki*32 + kj];
        M = fmaxf(M, sv[ki]);
    }
#pragma unroll
    for (int o = 16; o; o >>= 1)
        M = fmaxf(M, __shfl_xor_sync(0xffffffffu, M, o));

    float cle = 0.f, cge = 0.f;
#pragma unroll
    for (int ki = 0; ki < 32; ki++) {
        float e = __expf(sv[ki] - M);
        if (ki <= r) cle += e;
        if (ki >= r) cge += e;
    }
    bool jle = (kj <= c), jge = (kj >= c);
    float z00 = jle ? cle : 0.f;
    float z01 = jge ? cle : 0.f;
    float z10 = jle ? cge : 0.f;
    float z11 = jge ? cge : 0.f;
#pragma unroll
    for (int o = 16; o; o >>= 1) {
        z00 += __shfl_xor_sync(0xffffffffu, z00, o);
        z01 += __shfl_xor_sync(0xffffffffu, z01, o);
        z10 += __shfl_xor_sync(0xffffffffu, z10, o);
        z11 += __shfl_xor_sync(0xffffffffu, z11, o);
    }
    if (lane == 0) {
        float* st = g_stats + ((size_t)z*SEQ + q)*8;
        st[0] = M;
        st[1] = 0.25f / z00;
        st[2] = 0.25f / z01;
        st[3] = 0.25f / z10;
        st[4] = 0.25f / z11;
    }
}

// ---------------- AV fused: O = softmax-combine(S) @ V ----------------
// BK=32 == image width, so key-row predicate (ki vs r) is uniform per k-tile.
#define AV_ALD 36
#define AV_BLD 72
#define AV_AS_W   (2*128*AV_ALD)                   // 9216 words
#define AV_BS_W   (2*32*AV_BLD)                    // 4608 words
#define AV_MS_OFF (AV_AS_W + AV_BS_W)              // Ms[128]
#define AV_CA_OFF (AV_MS_OFF + 128)                // Ca[128][4]
#define AV_SMEM   ((AV_CA_OFF + 512)*4)            // 57856 bytes

__global__ __launch_bounds__(256) void av_fused() {
    extern __shared__ uint32_t sm[];
    uint32_t (*As)[128][AV_ALD] = (uint32_t(*)[128][AV_ALD])sm;
    uint32_t (*Bs)[32][AV_BLD]  = (uint32_t(*)[32][AV_BLD])(sm + AV_AS_W);
    float* Ms = (float*)(sm + AV_MS_OFF);
    float (*Ca)[4] = (float(*)[4])(sm + AV_CA_OFF);

    const int z = blockIdx.z;
    const int row0 = blockIdx.y*128;
    const int tid = threadIdx.x, lane = tid & 31, wid = tid >> 5;
    const int g = lane >> 2, tg = lane & 3;
    const int wr = wid >> 1, wc = wid & 1;         // WM=32 (4 grp), WN=32 (2 grp)

    const float* Sg = g_s + (size_t)z*SEQ*SEQ;
    const float* Vg = g_v + (size_t)z*SEQ*DH;
    const float* St = g_stats + (size_t)z*SEQ*8;

    // load per-row stats
    if (tid < 128) {
        const float* st = St + (size_t)(row0 + tid)*8;
        Ms[tid]   = st[0];
        Ca[tid][0] = st[1];
        Ca[tid][1] = st[2];
        Ca[tid][2] = st[3];
        Ca[tid][3] = st[4];
    }
    __syncthreads();

    float acc[2][4][4];
#pragma unroll
    for (int mi = 0; mi < 2; mi++)
#pragma unroll
        for (int ni = 0; ni < 4; ni++)
#pragma unroll
            for (int rr = 0; rr < 4; rr++) acc[mi][ni][rr] = 0.f;

    // transform+store of one A float4 (rowLocal r, in-tile col kq*4, tile t)
    auto storeA = [&](int buf, int t, int i, float4 v) {
        int idx = tid + i*256;
        int r = idx >> 3, kq = idx & 7;
        int qrow = row0 + r;
        int rimg = qrow >> 5, cimg = qrow & 31;
        float Mv = Ms[r];
        float a00 = Ca[r][0], a01 = Ca[r][1], a10 = Ca[r][2], a11 = Ca[r][3];
        float sv[4] = {v.x, v.y, v.z, v.w};
#pragma unroll
        for (int j = 0; j < 4; j++) {
            int kj = kq*4 + j;                    // ki == t (tile-uniform)
            float e = __expf(sv[j] - Mv);
            float ct = (kj <= cimg ? a00 : 0.f) + (kj >= cimg ? a01 : 0.f);
            float cb = (kj <= cimg ? a10 : 0.f) + (kj >= cimg ? a11 : 0.f);
            float coef = (t <= rimg ? ct : 0.f) + (t >= rimg ? cb : 0.f);
            As[buf][r][kq*4+j] = f2tf32(e * coef);
        }
    };

    // preload tile 0
#pragma unroll
    for (int i = 0; i < 4; i++) {
        int idx = tid + i*256;
        int r = idx >> 3, kq = idx & 7;
        float4 v = *(const float4*)(Sg + (size_t)(row0+r)*SEQ + kq*4);
        storeA(0, 0, i, v);
    }
#pragma unroll
    for (int i = 0; i < 2; i++) {
        int idx = tid + i*256;
        int kr = idx >> 4, d4 = idx & 15;
        float4 v = *(const float4*)(Vg + (size_t)kr*DH + d4*4);
        Bs[0][kr][d4*4+0] = f2tf32(v.x);
        Bs[0][kr][d4*4+1] = f2tf32(v.y);
        Bs[0][kr][d4*4+2] = f2tf32(v.z);
        Bs[0][kr][d4*4+3] = f2tf32(v.w);
    }
    __syncthreads();

    float4 ar[4], br[2];
    for (int kt = 0; kt < 32; kt++) {
        const int buf = kt & 1;
        if (kt + 1 < 32) {
#pragma unroll
            for (int i = 0; i < 4; i++) {
                int idx = tid + i*256;
                int r = idx >> 3, kq = idx & 7;
                ar[i] = *(const float4*)(Sg + (size_t)(row0+r)*SEQ + (kt+1)*32 + kq*4);
            }
#pragma unroll
            for (int i = 0; i < 2; i++) {
                int idx = tid + i*256;
                int kr = idx >> 4, d4 = idx & 15;
                br[i] = *(const float4*)(Vg + (size_t)((kt+1)*32+kr)*DH + d4*4);
            }
        }
#pragma unroll
        for (int ks = 0; ks < 4; ks++) {
            uint32_t af[2][4], bf[4][2];
#pragma unroll
            for (int mi = 0; mi < 2; mi++) {
                int m0 = wr*32 + mi*16;
                af[mi][0] = (*As)[0][0];  // placeholder (overwritten below)
                af[mi][0] = As[buf][m0+g  ][ks*8+tg  ];
                af[mi][1] = As[buf][m0+g+8][ks*8+tg  ];
                af[mi][2] = As[buf][m0+g  ][ks*8+tg+4];
                af[mi][3] = As[buf][m0+g+8][ks*8+tg+4];
            }
#pragma unroll
            for (int ni = 0; ni < 4; ni++) {
                int n0 = wc*32 + ni*8;
                bf[ni][0] = Bs[buf][ks*8+tg  ][n0+g];
                bf[ni][1] = Bs[buf][ks*8+tg+4][n0+g];
            }
#pragma unroll
            for (int mi = 0; mi < 2; mi++)
#pragma unroll
                for (int ni = 0; ni < 4; ni++)
                    mma_tf32(acc[mi][ni], af[mi], bf[ni]);
        }
        if (kt + 1 < 32) {
#pragma unroll
            for (int i = 0; i < 4; i++) storeA(buf^1, kt+1, i, ar[i]);
#pragma unroll
            for (int i = 0; i < 2; i++) {
                int idx = tid + i*256;
                int kr = idx >> 4, d4 = idx & 15;
                Bs[buf^1][kr][d4*4+0] = f2tf32(br[i].x);
                Bs[buf^1][kr][d4*4+1] = f2tf32(br[i].y);
                Bs[buf^1][kr][d4*4+2] = f2tf32(br[i].z);
                Bs[buf^1][kr][d4*4+3] = f2tf32(br[i].w);
            }
        }
        __syncthreads();
    }

    // epilogue: O -> g_o[b][q][h*64+d]
    int bb = z / HEADS, h = z % HEADS;
#pragma unroll
    for (int mi = 0; mi < 2; mi++)
#pragma unroll
        for (int ni = 0; ni < 4; ni++)
#pragma unroll
            for (int rr = 0; rr < 4; rr++) {
                int n = row0 + wr*32 + mi*16 + g + (rr>>1)*8;
                int d = wc*32 + ni*8 + tg*2 + (rr&1);
                g_o[((size_t)bb*SEQ + n)*INNER + h*DH + d] = acc[mi][ni][rr];
            }
}

// ---------------- output projection ----------------
__global__ __launch_bounds__(256) void out_gemm(const float* __restrict__ w,
                                                const float* __restrict__ bias,
                                                float* __restrict__ outp) {
    constexpr int WM = 64, WN = 32, MI = WM/16, NI = WN/8;
    float acc[MI][NI][4];
    int row0 = blockIdx.y*128, col0 = blockIdx.x*128;
    gemm_db<128,128,16,WM,WN>(g_o, w, INNER, INNER, DIM, row0, col0, acc);
    const int lane = threadIdx.x & 31, wid = threadIdx.x >> 5;
    const int g = lane >> 2, tg = lane & 3;
    const int wr = wid / 4, wc = wid % 4;
#pragma unroll
    for (int mi = 0; mi < MI; mi++)
#pragma unroll
        for (int ni = 0; ni < NI; ni++)
#pragma unroll
            for (int rr = 0; rr < 4; rr++) {
                int r = row0 + wr*WM + mi*16 + g + (rr>>1)*8;
                int c = col0 + wc*WN + ni*8 + tg*2 + (rr&1);
                outp[(size_t)r*DIM + c] = acc[mi][ni][rr] + bias[c];
            }
}

// ---------------- launch ----------------
extern "C" void kernel_launch(void* const* d_in, const int* in_sizes, int n_in,
                              void* d_out, int out_size) {
    const float* x     = (const float*)d_in[0];
    const float* ln_g  = (const float*)d_in[1];
    const float* ln_b  = (const float*)d_in[2];
    const float* w_qkv = (const float*)d_in[3];
    const float* b_qkv = (const float*)d_in[4];
    const float* w_out = (const float*)d_in[5];
    const float* b_out = (const float*)d_in[6];
    float* outp = (float*)d_out;

    static bool attr_set = false;
    if (!attr_set) {
        cudaFuncSetAttribute(scores_gemm,
                             cudaFuncAttributeMaxDynamicSharedMemorySize, SC_SMEM);
        cudaFuncSetAttribute(av_fused,
                             cudaFuncAttributeMaxDynamicSharedMemorySize, AV_SMEM);
        attr_set = true;
    }

    ln_kernel<<<BATCH*SEQ, 128>>>(x, ln_g, ln_b);
    qkv_gemm<<<dim3((3*INNER)/128, (BATCH*SEQ)/128), 256>>>(w_qkv, b_qkv);
    scores_gemm<<<dim3(SEQ/128, SEQ/128, BH), 256, SC_SMEM>>>();
    stats_kernel<<<dim3(SEQ/8, BH), 256>>>();
    av_fused<<<dim3(1, SEQ/128, BH), 256, AV_SMEM>>>();
    out_gemm<<<dim3(DIM/128, (BATCH*SEQ)/128), 256>>>(w_out, b_out, outp);
}